// round 1
// baseline (speedup 1.0000x reference)
#include <cuda_runtime.h>

#define CAP    65536
#define HID    512
#define NH     8
#define BATCH  2048
#define TOPK   32
#define NCODE  256
#define CHUNK  256
#define NCHUNK (CAP / CHUNK)

// ---------------- scratch (static device globals; no allocation) ----------------
__device__ float         g_W[NH * HID];          // presummed hash weights [8][512]
__device__ unsigned char g_qcode[BATCH];
__device__ unsigned char g_kcode[CAP];
__device__ int           g_hist[NCHUNK][NCODE];  // per-chunk hist -> per-chunk base
__device__ int           g_bstart[NCODE];
__device__ int           g_bcnt[NCODE];
__device__ int           g_sorted[CAP];          // key indices, stable-sorted by code
__device__ float         g_memout[BATCH * HID];  // attention output before final linear

// ---------------- K1: W[n][h] = sum_d hash_projections[n][h][d] ----------------
__global__ void k_reduce_w(const float* __restrict__ hp) {
    int i = blockIdx.x * blockDim.x + threadIdx.x;
    if (i < NH * HID) {
        float s = 0.f;
#pragma unroll
        for (int d = 0; d < 16; d++) s += hp[i * 16 + d];
        g_W[i] = s;
    }
}

// ---------------- K2: 8-bit LSH code per row (1 warp per row) ----------------
__global__ void k_hash(const float* __restrict__ X, int rows, int isQuery) {
    __shared__ float sW[NH * HID];
    int tid = threadIdx.x;
    for (int i = tid; i < NH * HID; i += blockDim.x) sW[i] = g_W[i];
    __syncthreads();
    int warp = tid >> 5, lane = tid & 31;
    int row = blockIdx.x * 8 + warp;
    if (row >= rows) return;
    const float* x = X + (size_t)row * HID;
    float acc[NH];
#pragma unroll
    for (int n = 0; n < NH; n++) acc[n] = 0.f;
    for (int h = lane; h < HID; h += 32) {
        float v = x[h];
#pragma unroll
        for (int n = 0; n < NH; n++) acc[n] += v * sW[n * HID + h];
    }
#pragma unroll
    for (int n = 0; n < NH; n++) {
#pragma unroll
        for (int off = 16; off > 0; off >>= 1)
            acc[n] += __shfl_xor_sync(0xffffffffu, acc[n], off);
    }
    if (lane == 0) {
        unsigned c = 0;
#pragma unroll
        for (int n = 0; n < NH; n++)
            if (acc[n] > 0.f) c |= (1u << n);
        if (isQuery) g_qcode[row] = (unsigned char)c;
        else         g_kcode[row] = (unsigned char)c;
    }
}

// ---------------- K3a: per-chunk code histogram ----------------
__global__ void k_hist(void) {
    __shared__ int sh[NCODE];
    int tid = threadIdx.x;
    sh[tid] = 0;
    __syncthreads();
    int c = g_kcode[blockIdx.x * CHUNK + tid];
    atomicAdd(&sh[c], 1);
    __syncthreads();
    g_hist[blockIdx.x][tid] = sh[tid];
}

// ---------------- K3b: scan -> bucket starts + per-chunk bases (1 block) --------
__global__ void k_scan(void) {
    int tid = threadIdx.x;  // tid == code
    int run = 0;
    for (int c = 0; c < NCHUNK; c++) {
        int v = g_hist[c][tid];
        g_hist[c][tid] = run;   // chunk-local exclusive prefix for this code
        run += v;
    }
    __shared__ int s[NCODE];
    s[tid] = run;
    __syncthreads();
    for (int off = 1; off < NCODE; off <<= 1) {  // inclusive Hillis-Steele
        int v = (tid >= off) ? s[tid - off] : 0;
        __syncthreads();
        s[tid] += v;
        __syncthreads();
    }
    int start = s[tid] - run;  // exclusive
    g_bstart[tid] = start;
    g_bcnt[tid] = run;
    for (int c = 0; c < NCHUNK; c++) g_hist[c][tid] += start;
}

// ---------------- K3c: stable scatter by code ----------------
__global__ void k_scatter(void) {
    __shared__ unsigned char sc[CHUNK];
    int tid = threadIdx.x;
    int gi = blockIdx.x * CHUNK + tid;
    sc[tid] = g_kcode[gi];
    __syncthreads();
    int my = sc[tid];
    int rank = 0;
    for (int i = 0; i < tid; i++) rank += (sc[i] == my);
    g_sorted[g_hist[blockIdx.x][my] + rank] = gi;
}

// ---------------- K4: select top-32, attention over them (1 block / query) ------
__global__ void k_attn(const float* __restrict__ query,
                       const float* __restrict__ mkeys,
                       const float* __restrict__ mvals) {
    int b = blockIdx.x, tid = threadIdx.x;
    __shared__ int   sidx[TOPK];
    __shared__ float sq[HID];
    __shared__ float ssc[TOPK];
    __shared__ float swt[TOPK];

    int code = g_qcode[b];
    int cnt = g_bcnt[code];
    if (cnt >= TOPK) {
        if (tid < TOPK) sidx[tid] = g_sorted[g_bstart[code] + tid];
    } else if (tid < 32) {
        // Rare fallback: exact (distance, index)-ordered selection by full scan.
        int lane = tid;
        int got = 0;
        for (int d = 0; d <= NH && got < TOPK; d++) {
            for (int base = 0; base < CAP; base += 32) {
                int c = g_kcode[base + lane];
                bool hit = (__popc(c ^ code) == d);
                unsigned m = __ballot_sync(0xffffffffu, hit);
                int r = __popc(m & ((1u << lane) - 1u));
                if (hit && got + r < TOPK) sidx[got + r] = base + lane;
                got += __popc(m);
                if (got >= TOPK) break;
            }
        }
    }
    for (int i = tid; i < HID; i += blockDim.x) sq[i] = query[b * HID + i];
    __syncthreads();

    // scores: 8 threads per key, float4 dot
    {
        int k = tid >> 3, sub = tid & 7;
        const float4* kr = (const float4*)(mkeys + (size_t)sidx[k] * HID);
        const float4* q4 = (const float4*)sq;
        float acc = 0.f;
#pragma unroll
        for (int j = sub; j < HID / 4; j += 8) {
            float4 a = kr[j];
            float4 qv = q4[j];
            acc += a.x * qv.x + a.y * qv.y + a.z * qv.z + a.w * qv.w;
        }
        acc += __shfl_xor_sync(0xffffffffu, acc, 1);
        acc += __shfl_xor_sync(0xffffffffu, acc, 2);
        acc += __shfl_xor_sync(0xffffffffu, acc, 4);
        if (sub == 0) ssc[k] = acc * 0.04419417382415922f;  // 1/sqrt(512)
    }
    __syncthreads();

    if (tid < 32) {  // softmax over 32 scores
        float s = ssc[tid];
        float mx = s;
#pragma unroll
        for (int off = 16; off > 0; off >>= 1)
            mx = fmaxf(mx, __shfl_xor_sync(0xffffffffu, mx, off));
        float e = expf(s - mx);
        float sum = e;
#pragma unroll
        for (int off = 16; off > 0; off >>= 1)
            sum += __shfl_xor_sync(0xffffffffu, sum, off);
        swt[tid] = e / sum;
    }
    __syncthreads();

    // weighted sum of values: each thread owns 2 output elements
    float o0 = 0.f, o1 = 0.f;
#pragma unroll 4
    for (int k = 0; k < TOPK; k++) {
        float w = swt[k];
        const float* vr = mvals + (size_t)sidx[k] * HID;
        o0 += w * vr[tid];
        o1 += w * vr[tid + 256];
    }
    g_memout[b * HID + tid] = o0;
    g_memout[b * HID + tid + 256] = o1;
}

// ---------------- K5: out = memout @ out_w^T + b  (NT SGEMM, 64x64x32 tiles) ----
__global__ void k_gemm(const float* __restrict__ Wt,
                       const float* __restrict__ bias,
                       float* __restrict__ C) {
    const int BM = 64, BN = 64, BK = 32;
    __shared__ float As[BK][BM + 4];
    __shared__ float Bs[BK][BN + 4];
    int tid = threadIdx.x;                 // 256 threads
    int bm = blockIdx.y * BM, bn = blockIdx.x * BN;
    int tm = tid >> 4, tn = tid & 15;
    float acc[4][4];
#pragma unroll
    for (int i = 0; i < 4; i++)
#pragma unroll
        for (int j = 0; j < 4; j++) acc[i][j] = 0.f;

    for (int k0 = 0; k0 < HID; k0 += BK) {
#pragma unroll
        for (int t = 0; t < 2; t++) {
            int idx = tid + t * 256;       // 0..511 float4 slots (64 rows x 8)
            int row = idx >> 3;
            int kq = (idx & 7) * 4;
            float4 a = *(const float4*)&g_memout[(size_t)(bm + row) * HID + k0 + kq];
            As[kq + 0][row] = a.x; As[kq + 1][row] = a.y;
            As[kq + 2][row] = a.z; As[kq + 3][row] = a.w;
            float4 bb = *(const float4*)&Wt[(size_t)(bn + row) * HID + k0 + kq];
            Bs[kq + 0][row] = bb.x; Bs[kq + 1][row] = bb.y;
            Bs[kq + 2][row] = bb.z; Bs[kq + 3][row] = bb.w;
        }
        __syncthreads();
#pragma unroll
        for (int kk = 0; kk < BK; kk++) {
            float4 a = *(const float4*)&As[kk][tm * 4];
            float4 bv = *(const float4*)&Bs[kk][tn * 4];
            float av[4] = {a.x, a.y, a.z, a.w};
            float bvv[4] = {bv.x, bv.y, bv.z, bv.w};
#pragma unroll
            for (int i = 0; i < 4; i++)
#pragma unroll
                for (int j = 0; j < 4; j++) acc[i][j] += av[i] * bvv[j];
        }
        __syncthreads();
    }
#pragma unroll
    for (int i = 0; i < 4; i++) {
#pragma unroll
        for (int j = 0; j < 4; j++) {
            C[(size_t)(bm + tm * 4 + i) * HID + bn + tn * 4 + j] =
                acc[i][j] + bias[bn + tn * 4 + j];
        }
    }
}

// ---------------- launch ----------------
extern "C" void kernel_launch(void* const* d_in, const int* in_sizes, int n_in,
                              void* d_out, int out_size) {
    const float* query = (const float*)d_in[0];
    const float* mkeys = (const float*)d_in[1];
    const float* mvals = (const float*)d_in[2];
    const float* hproj = (const float*)d_in[3];
    const float* outw  = (const float*)d_in[4];
    const float* outb  = (const float*)d_in[5];
    float* out = (float*)d_out;

    k_reduce_w<<<(NH * HID + 255) / 256, 256>>>(hproj);
    k_hash<<<(CAP + 7) / 8, 256>>>(mkeys, CAP, 0);
    k_hash<<<(BATCH + 7) / 8, 256>>>(query, BATCH, 1);
    k_hist<<<NCHUNK, CHUNK>>>();
    k_scan<<<1, NCODE>>>();
    k_scatter<<<NCHUNK, CHUNK>>>();
    k_attn<<<BATCH, 256>>>(query, mkeys, mvals);
    dim3 ggrid(HID / 64, BATCH / 64);
    k_gemm<<<ggrid, 256>>>(outw, outb, out);
}

// round 2
// speedup vs baseline: 1.2470x; 1.2470x over previous
#include <cuda_runtime.h>

#define CAP    65536
#define HID    512
#define NH     8
#define BATCH  2048
#define TOPK   32
#define NCODE  256
#define CHUNK  256
#define NCHUNK (CAP / CHUNK)
#define QCHUNK (BATCH / CHUNK)

// ---------------- scratch (static device globals; no allocation) ----------------
__device__ float         g_W[NH * HID];
__device__ unsigned char g_qcode[BATCH];
__device__ unsigned char g_kcode[CAP];
__device__ int           g_hist[NCHUNK * NCODE];
__device__ int           g_bstart[NCODE];
__device__ int           g_bcnt[NCODE];
__device__ int           g_sorted[CAP];
__device__ int           g_qhist[QCHUNK * NCODE];
__device__ int           g_qbstart[NCODE];
__device__ int           g_qbcnt[NCODE];
__device__ int           g_qsorted[BATCH];
__device__ float         g_memout[BATCH * HID];

// ---------------- K1: W[n][h] = sum_d hp[n][h][d] ----------------
__global__ void k_reduce_w(const float* __restrict__ hp) {
    int i = blockIdx.x * blockDim.x + threadIdx.x;
    if (i < NH * HID) {
        float s = 0.f;
#pragma unroll
        for (int d = 0; d < 16; d++) s += hp[i * 16 + d];
        g_W[i] = s;
    }
}

// ---------------- K2: LSH code, 4 rows per warp (FFMA-bound) ----------------
__global__ void k_hash(const float* __restrict__ X, int rows, unsigned char* __restrict__ out) {
    __shared__ float4 sW4[NH * 128];
    int tid = threadIdx.x;
    for (int i = tid; i < NH * 128; i += 256) sW4[i] = ((const float4*)g_W)[i];
    __syncthreads();
    int warp = tid >> 5, lane = tid & 31;
    int r0 = blockIdx.x * 32 + warp * 4;
    if (r0 >= rows) return;
    float acc[4][NH];
#pragma unroll
    for (int r = 0; r < 4; r++)
#pragma unroll
        for (int n = 0; n < NH; n++) acc[r][n] = 0.f;

#pragma unroll
    for (int i = 0; i < 4; i++) {
        int j = lane + 32 * i;   // float4 index within row (0..127)
        float4 xv[4];
#pragma unroll
        for (int r = 0; r < 4; r++)
            xv[r] = ((const float4*)(X + (size_t)(r0 + r) * HID))[j];
#pragma unroll
        for (int n = 0; n < NH; n++) {
            float4 wv = sW4[n * 128 + j];
#pragma unroll
            for (int r = 0; r < 4; r++)
                acc[r][n] += xv[r].x * wv.x + xv[r].y * wv.y + xv[r].z * wv.z + xv[r].w * wv.w;
        }
    }
#pragma unroll
    for (int r = 0; r < 4; r++)
#pragma unroll
        for (int n = 0; n < NH; n++) {
#pragma unroll
            for (int off = 16; off > 0; off >>= 1)
                acc[r][n] += __shfl_xor_sync(0xffffffffu, acc[r][n], off);
        }
    if (lane == 0) {
#pragma unroll
        for (int r = 0; r < 4; r++) {
            unsigned c = 0;
#pragma unroll
            for (int n = 0; n < NH; n++)
                if (acc[r][n] > 0.f) c |= (1u << n);
            out[r0 + r] = (unsigned char)c;
        }
    }
}

// ---------------- K3: generalized counting sort by code ----------------
__global__ void k_hist_g(const unsigned char* __restrict__ codes, int* __restrict__ hist) {
    __shared__ int sh[NCODE];
    int tid = threadIdx.x;
    sh[tid] = 0;
    __syncthreads();
    atomicAdd(&sh[codes[blockIdx.x * CHUNK + tid]], 1);
    __syncthreads();
    hist[blockIdx.x * NCODE + tid] = sh[tid];
}

__global__ void k_scan_g(int* __restrict__ hist, int* __restrict__ bstart,
                         int* __restrict__ bcnt, int nchunk) {
    int tid = threadIdx.x;  // == code
    int run = 0;
    for (int c = 0; c < nchunk; c++) {
        int v = hist[c * NCODE + tid];
        hist[c * NCODE + tid] = run;
        run += v;
    }
    __shared__ int s[NCODE];
    s[tid] = run;
    __syncthreads();
    for (int off = 1; off < NCODE; off <<= 1) {
        int v = (tid >= off) ? s[tid - off] : 0;
        __syncthreads();
        s[tid] += v;
        __syncthreads();
    }
    int start = s[tid] - run;
    bstart[tid] = start;
    bcnt[tid] = run;
    for (int c = 0; c < nchunk; c++) hist[c * NCODE + tid] += start;
}

__global__ void k_scatter_g(const unsigned char* __restrict__ codes,
                            const int* __restrict__ hist, int* __restrict__ sorted) {
    __shared__ unsigned char sc[CHUNK];
    int tid = threadIdx.x;
    int gi = blockIdx.x * CHUNK + tid;
    sc[tid] = codes[gi];
    __syncthreads();
    int my = sc[tid];
    int rank = 0;
    for (int i = 0; i < tid; i++) rank += (sc[i] == my);
    sorted[hist[blockIdx.x * NCODE + my] + rank] = gi;
}

// ---------------- K4: grouped attention (1 block per code x 8-query group) ------
__global__ void k_attn(const float* __restrict__ query,
                       const float* __restrict__ mkeys,
                       const float* __restrict__ mvals) {
    int code = blockIdx.x;
    int qcnt = g_qbcnt[code];
    if ((int)blockIdx.y * 8 >= qcnt) return;
    int tid = threadIdx.x;

    __shared__ int   sidx[TOPK];
    __shared__ float sq[8][HID];
    __shared__ float ssc[8][TOPK];
    __shared__ float swt[8][TOPK];
    __shared__ int   sqi[8];

    int kcnt = g_bcnt[code];
    if (kcnt >= TOPK) {
        if (tid < TOPK) sidx[tid] = g_sorted[g_bstart[code] + tid];
    } else if (tid < 32) {
        // exact (distance, index)-ordered fallback, astronomically rare
        int lane = tid;
        int got = 0;
        for (int d = 0; d <= NH && got < TOPK; d++) {
            for (int base = 0; base < CAP; base += 32) {
                int c = g_kcode[base + lane];
                bool hit = (__popc(c ^ code) == d);
                unsigned m = __ballot_sync(0xffffffffu, hit);
                int r = __popc(m & ((1u << lane) - 1u));
                if (hit && got + r < TOPK) sidx[got + r] = base + lane;
                got += __popc(m);
                if (got >= TOPK) break;
            }
        }
    }

    int qbase = g_qbstart[code];
    for (int g = blockIdx.y; g * 8 < qcnt; g += 32) {
        int qs = g * 8;
        int nq = qcnt - qs; if (nq > 8) nq = 8;
        if (tid < nq) sqi[tid] = g_qsorted[qbase + qs + tid];
        __syncthreads();
        // load nq query rows
        for (int i = tid; i < nq * HID; i += 256) {
            int q = i >> 9, h = i & (HID - 1);
            sq[q][h] = query[(size_t)sqi[q] * HID + h];
        }
        __syncthreads();

        // scores: 128 active threads, 2 keys x 8 partial-subsets each
        if (tid < 128) {
            int sub = tid & 7, kg = tid >> 3;  // kg 0..15 -> keys kg, kg+16
            const float4* kr0 = (const float4*)(mkeys + (size_t)sidx[kg] * HID);
            const float4* kr1 = (const float4*)(mkeys + (size_t)sidx[kg + 16] * HID);
            float a0[8], a1[8];
#pragma unroll
            for (int q = 0; q < 8; q++) { a0[q] = 0.f; a1[q] = 0.f; }
#pragma unroll
            for (int j = 0; j < 16; j++) {
                int jj = sub + 8 * j;
                float4 k0 = kr0[jj];
                float4 k1 = kr1[jj];
#pragma unroll
                for (int q = 0; q < 8; q++) {
                    float4 qv = ((const float4*)sq[q])[jj];
                    a0[q] += k0.x * qv.x + k0.y * qv.y + k0.z * qv.z + k0.w * qv.w;
                    a1[q] += k1.x * qv.x + k1.y * qv.y + k1.z * qv.z + k1.w * qv.w;
                }
            }
#pragma unroll
            for (int q = 0; q < 8; q++) {
#pragma unroll
                for (int off = 1; off < 8; off <<= 1) {
                    a0[q] += __shfl_xor_sync(0xffffffffu, a0[q], off);
                    a1[q] += __shfl_xor_sync(0xffffffffu, a1[q], off);
                }
            }
            if (sub == 0) {
#pragma unroll
                for (int q = 0; q < 8; q++) {
                    ssc[q][kg]      = a0[q] * 0.04419417382415922f;
                    ssc[q][kg + 16] = a1[q] * 0.04419417382415922f;
                }
            }
        }
        __syncthreads();

        // softmax: warp per query
        {
            int q = tid >> 5, lane = tid & 31;
            float s = ssc[q][lane];
            float mx = s;
#pragma unroll
            for (int off = 16; off > 0; off >>= 1)
                mx = fmaxf(mx, __shfl_xor_sync(0xffffffffu, mx, off));
            float e = expf(s - mx);
            float sum = e;
#pragma unroll
            for (int off = 16; off > 0; off >>= 1)
                sum += __shfl_xor_sync(0xffffffffu, sum, off);
            swt[q][lane] = e / sum;
        }
        __syncthreads();

        // values: thread owns 2 output cols x 8 queries
        float o0[8], o1[8];
#pragma unroll
        for (int q = 0; q < 8; q++) { o0[q] = 0.f; o1[q] = 0.f; }
#pragma unroll 4
        for (int k = 0; k < TOPK; k++) {
            const float* vr = mvals + (size_t)sidx[k] * HID;
            float v0 = vr[tid];
            float v1 = vr[tid + 256];
#pragma unroll
            for (int q = 0; q < 8; q++) {
                float w = swt[q][k];
                o0[q] += w * v0;
                o1[q] += w * v1;
            }
        }
        for (int q = 0; q < nq; q++) {
            g_memout[(size_t)sqi[q] * HID + tid]       = o0[q];
            g_memout[(size_t)sqi[q] * HID + tid + 256] = o1[q];
        }
        __syncthreads();
    }
}

// ---------------- K5: out = memout @ W^T + b; 64x64x32, 8x4 micro, dbl-buffered -
__global__ void k_gemm(const float* __restrict__ Wt,
                       const float* __restrict__ bias,
                       float* __restrict__ C) {
    const int BM = 64, BN = 64, BK = 32;
    __shared__ float As[2][BK][BM + 4];
    __shared__ float Bs[2][BK][BN + 4];
    int tid = threadIdx.x;              // 128 threads
    int bm = blockIdx.y * BM, bn = blockIdx.x * BN;
    int tmg = tid >> 4;                 // 0..7  -> 8 rows
    int tng = tid & 15;                 // 0..15 -> 4 cols
    float acc[8][4];
#pragma unroll
    for (int i = 0; i < 8; i++)
#pragma unroll
        for (int j = 0; j < 4; j++) acc[i][j] = 0.f;

    float4 pa[4], pb[4];
    int lrow[4], lkq[4];
#pragma unroll
    for (int t = 0; t < 4; t++) {
        int idx = tid + t * 128;
        lrow[t] = idx >> 3;
        lkq[t] = (idx & 7) * 4;
    }

#define LOADSTEP(k0)                                                               \
    {                                                                              \
        _Pragma("unroll")                                                          \
        for (int t = 0; t < 4; t++) {                                              \
            pa[t] = *(const float4*)&g_memout[(size_t)(bm + lrow[t]) * HID + (k0) + lkq[t]]; \
            pb[t] = *(const float4*)&Wt[(size_t)(bn + lrow[t]) * HID + (k0) + lkq[t]];       \
        }                                                                          \
    }
#define STORESTEP(buf)                                                             \
    {                                                                              \
        _Pragma("unroll")                                                          \
        for (int t = 0; t < 4; t++) {                                              \
            As[buf][lkq[t] + 0][lrow[t]] = pa[t].x;                                \
            As[buf][lkq[t] + 1][lrow[t]] = pa[t].y;                                \
            As[buf][lkq[t] + 2][lrow[t]] = pa[t].z;                                \
            As[buf][lkq[t] + 3][lrow[t]] = pa[t].w;                                \
            Bs[buf][lkq[t] + 0][lrow[t]] = pb[t].x;                                \
            Bs[buf][lkq[t] + 1][lrow[t]] = pb[t].y;                                \
            Bs[buf][lkq[t] + 2][lrow[t]] = pb[t].z;                                \
            Bs[buf][lkq[t] + 3][lrow[t]] = pb[t].w;                                \
        }                                                                          \
    }

    LOADSTEP(0);
    STORESTEP(0);
    __syncthreads();
    int cur = 0;
    for (int s = 0; s < HID / BK; s++) {
        if (s < HID / BK - 1) LOADSTEP((s + 1) * BK);
#pragma unroll
        for (int kk = 0; kk < BK; kk++) {
            float4 a0 = *(const float4*)&As[cur][kk][tmg * 8];
            float4 a1 = *(const float4*)&As[cur][kk][tmg * 8 + 4];
            float4 b0 = *(const float4*)&Bs[cur][kk][tng * 4];
            float av[8] = {a0.x, a0.y, a0.z, a0.w, a1.x, a1.y, a1.z, a1.w};
            float bv[4] = {b0.x, b0.y, b0.z, b0.w};
#pragma unroll
            for (int i = 0; i < 8; i++)
#pragma unroll
                for (int j = 0; j < 4; j++) acc[i][j] += av[i] * bv[j];
        }
        if (s < HID / BK - 1) {
            STORESTEP(1 - cur);
            __syncthreads();
            cur ^= 1;
        }
    }
    float bb[4];
#pragma unroll
    for (int j = 0; j < 4; j++) bb[j] = bias[bn + tng * 4 + j];
#pragma unroll
    for (int i = 0; i < 8; i++)
#pragma unroll
        for (int j = 0; j < 4; j++)
            C[(size_t)(bm + tmg * 8 + i) * HID + bn + tng * 4 + j] = acc[i][j] + bb[j];
}

// ---------------- launch ----------------
extern "C" void kernel_launch(void* const* d_in, const int* in_sizes, int n_in,
                              void* d_out, int out_size) {
    const float* query = (const float*)d_in[0];
    const float* mkeys = (const float*)d_in[1];
    const float* mvals = (const float*)d_in[2];
    const float* hproj = (const float*)d_in[3];
    const float* outw  = (const float*)d_in[4];
    const float* outb  = (const float*)d_in[5];
    float* out = (float*)d_out;

    unsigned char *qcode, *kcode;
    int *hist, *bstart, *bcnt, *sorted, *qhist, *qbstart, *qbcnt, *qsorted;
    cudaGetSymbolAddress((void**)&qcode, g_qcode);
    cudaGetSymbolAddress((void**)&kcode, g_kcode);
    cudaGetSymbolAddress((void**)&hist, g_hist);
    cudaGetSymbolAddress((void**)&bstart, g_bstart);
    cudaGetSymbolAddress((void**)&bcnt, g_bcnt);
    cudaGetSymbolAddress((void**)&sorted, g_sorted);
    cudaGetSymbolAddress((void**)&qhist, g_qhist);
    cudaGetSymbolAddress((void**)&qbstart, g_qbstart);
    cudaGetSymbolAddress((void**)&qbcnt, g_qbcnt);
    cudaGetSymbolAddress((void**)&qsorted, g_qsorted);

    k_reduce_w<<<(NH * HID + 255) / 256, 256>>>(hproj);
    k_hash<<<CAP / 32, 256>>>(mkeys, CAP, kcode);
    k_hash<<<BATCH / 32, 256>>>(query, BATCH, qcode);
    k_hist_g<<<NCHUNK, CHUNK>>>(kcode, hist);
    k_scan_g<<<1, NCODE>>>(hist, bstart, bcnt, NCHUNK);
    k_scatter_g<<<NCHUNK, CHUNK>>>(kcode, hist, sorted);
    k_hist_g<<<QCHUNK, CHUNK>>>(qcode, qhist);
    k_scan_g<<<1, NCODE>>>(qhist, qbstart, qbcnt, QCHUNK);
    k_scatter_g<<<QCHUNK, CHUNK>>>(qcode, qhist, qsorted);
    dim3 agrid(NCODE, 32);
    k_attn<<<agrid, 256>>>(query, mkeys, mvals);
    dim3 ggrid(HID / 64, BATCH / 64);
    k_gemm<<<ggrid, 128>>>(outw, outb, out);
}